// round 4
// baseline (speedup 1.0000x reference)
#include <cuda_runtime.h>

#define BATCH 4096
#define NCLS  10000
#define DIM   256
#define ALPHA 0.5f
#define CAP   64   // per-class row-list capacity (overflow handled exactly)

// Scratch (allocation-free: __device__ globals).
// g_cnt starts zeroed (static init) and is RESTORED to zero by
// scale_gather_loss_kernel at the end of every execution -> no zero kernel.
__device__ int g_cnt[NCLS];         // per-class sample count
__device__ int g_label[BATCH];      // decoded label per row (overflow fallback)
__device__ int g_rows[NCLS * CAP];  // per-class row index list

// ---------------------------------------------------------------------------
// K1: one block per batch row. Early-exit forward scan of the onehot row
// (float4, 4KB chunks). Finder thread records label, appends row to class
// list, bumps count. Pure scan: no tail gathers on the critical chain.
// ---------------------------------------------------------------------------
__global__ __launch_bounds__(256, 8)
void scan_kernel(const float* __restrict__ onehot) {
    const int b = blockIdx.x;
    const int t = threadIdx.x;

    __shared__ int s_label;
    if (t == 0) s_label = -1;
    __syncthreads();

    const float4* row = reinterpret_cast<const float4*>(onehot + (size_t)b * NCLS);
    const int NV4 = NCLS / 4;  // 2500

    #pragma unroll 1
    for (int it = 0; it < (NV4 + 255) / 256; ++it) {
        int i = it * 256 + t;
        if (i < NV4) {
            float4 v = row[i];
            int found = -1;
            if (v.x != 0.f)      found = 4 * i + 0;
            else if (v.y != 0.f) found = 4 * i + 1;
            else if (v.z != 0.f) found = 4 * i + 2;
            else if (v.w != 0.f) found = 4 * i + 3;
            if (found >= 0) {
                s_label = found;
                g_label[b] = found;
                int slot = atomicAdd(&g_cnt[found], 1);
                if (slot < CAP) g_rows[found * CAP + slot] = b;
            }
        }
        __syncthreads();
        if (s_label >= 0) break;
    }
}

// ---------------------------------------------------------------------------
// K2: one warp per class.
//   out_c = k*centers_c + s * sum(feat rows of class c)
//   loss[b] = ||feat_b - centers_c||^2  for each row b of class c (OLD center)
//   then g_cnt[c] = 0  (restore scratch for next graph replay)
//   k = 1 - ALPHA*n/(n+1), s = ALPHA/(n+1). Atomic-free, single write.
// ---------------------------------------------------------------------------
__global__ __launch_bounds__(256)
void scale_gather_loss_kernel(const float* __restrict__ centers,
                              const float* __restrict__ feat,
                              float* __restrict__ out_centers,
                              float* __restrict__ loss_out) {
    const int warp = (blockIdx.x * blockDim.x + threadIdx.x) >> 5;
    if (warp >= NCLS) return;
    const int lane = threadIdx.x & 31;

    const int n = g_cnt[warp];
    if (lane == 0) g_cnt[warp] = 0;  // self-clean for next replay

    const float fn = (float)n;
    const float k = 1.0f - ALPHA * fn / (fn + 1.0f);
    const float s = ALPHA / (fn + 1.0f);

    // old center row (8 dims per lane)
    const float4* crow = reinterpret_cast<const float4*>(centers + (size_t)warp * DIM);
    const float4 c0 = crow[lane];
    const float4 c1 = crow[lane + 32];

    float4 a0, a1;  // accumulator = k * old center
    a0.x = c0.x * k; a0.y = c0.y * k; a0.z = c0.z * k; a0.w = c0.w * k;
    a1.x = c1.x * k; a1.y = c1.y * k; a1.z = c1.z * k; a1.w = c1.w * k;

    if (n > 0) {
        if (n <= CAP) {
            #pragma unroll 1
            for (int j = 0; j < n; ++j) {
                int b = g_rows[warp * CAP + j];
                const float4* fr = reinterpret_cast<const float4*>(feat + (size_t)b * DIM);
                float4 f0 = fr[lane];
                float4 f1 = fr[lane + 32];
                // accumulate scaled features
                a0.x += s * f0.x; a0.y += s * f0.y; a0.z += s * f0.z; a0.w += s * f0.w;
                a1.x += s * f1.x; a1.y += s * f1.y; a1.z += s * f1.z; a1.w += s * f1.w;
                // loss vs OLD center
                float dx, sq;
                dx = f0.x - c0.x; sq  = dx * dx;
                dx = f0.y - c0.y; sq += dx * dx;
                dx = f0.z - c0.z; sq += dx * dx;
                dx = f0.w - c0.w; sq += dx * dx;
                dx = f1.x - c1.x; sq += dx * dx;
                dx = f1.y - c1.y; sq += dx * dx;
                dx = f1.z - c1.z; sq += dx * dx;
                dx = f1.w - c1.w; sq += dx * dx;
                #pragma unroll
                for (int off = 16; off > 0; off >>= 1)
                    sq += __shfl_down_sync(0xFFFFFFFFu, sq, off);
                if (lane == 0) loss_out[b] = sq;
            }
        } else {
            // exhaustive fallback (statistically unreachable; exact correctness)
            #pragma unroll 1
            for (int b = 0; b < BATCH; ++b) {
                if (g_label[b] == warp) {
                    const float4* fr = reinterpret_cast<const float4*>(feat + (size_t)b * DIM);
                    float4 f0 = fr[lane];
                    float4 f1 = fr[lane + 32];
                    a0.x += s * f0.x; a0.y += s * f0.y; a0.z += s * f0.z; a0.w += s * f0.w;
                    a1.x += s * f1.x; a1.y += s * f1.y; a1.z += s * f1.z; a1.w += s * f1.w;
                    float dx, sq;
                    dx = f0.x - c0.x; sq  = dx * dx;
                    dx = f0.y - c0.y; sq += dx * dx;
                    dx = f0.z - c0.z; sq += dx * dx;
                    dx = f0.w - c0.w; sq += dx * dx;
                    dx = f1.x - c1.x; sq += dx * dx;
                    dx = f1.y - c1.y; sq += dx * dx;
                    dx = f1.z - c1.z; sq += dx * dx;
                    dx = f1.w - c1.w; sq += dx * dx;
                    #pragma unroll
                    for (int off = 16; off > 0; off >>= 1)
                        sq += __shfl_down_sync(0xFFFFFFFFu, sq, off);
                    if (lane == 0) loss_out[b] = sq;
                }
            }
        }
    }

    float4* orow = reinterpret_cast<float4*>(out_centers + (size_t)warp * DIM);
    orow[lane]      = a0;
    orow[lane + 32] = a1;
}

// ---------------------------------------------------------------------------
extern "C" void kernel_launch(void* const* d_in, const int* in_sizes, int n_in,
                              void* d_out, int out_size) {
    const float* feat    = (const float*)d_in[0];  // [4096, 256]
    const float* onehot  = (const float*)d_in[1];  // [4096, 10000]
    const float* centers = (const float*)d_in[2];  // [10000, 256]

    float* loss_out    = (float*)d_out;            // [4096]
    float* centers_out = (float*)d_out + BATCH;    // [10000, 256]

    scan_kernel<<<BATCH, 256>>>(onehot);
    // 10000 classes, one warp each -> 1250 blocks of 256 threads
    scale_gather_loss_kernel<<<(NCLS * 32 + 255) / 256, 256>>>(
        centers, feat, centers_out, loss_out);
}

// round 5
// speedup vs baseline: 1.3665x; 1.3665x over previous
#include <cuda_runtime.h>

#define BATCH 4096
#define NCLS  10000
#define DIM   256
#define ALPHA 0.5f
#define CAP   64   // per-class row-list capacity (overflow handled exactly)

// Scratch (allocation-free: __device__ globals).
// g_cnt starts zeroed (static init) and is RESTORED to zero by
// scale_gather_kernel at the end of every execution -> no zero kernel needed.
__device__ int g_cnt[NCLS];         // per-class sample count
__device__ int g_label[BATCH];      // decoded label per row (overflow fallback)
__device__ int g_rows[NCLS * CAP];  // per-class row index list

// ---------------------------------------------------------------------------
// K1: one block per batch row.
//  a) early-exit scan of the onehot row, 8 KB chunks (2 float4 per thread per
//     iteration -> MLP=2, half the barriers of the 4 KB version)
//  b) finder thread: record label, append row to class list, bump count
//  c) all threads: loss ||feat - centers[label]||^2 (gather latency hides
//     under the BW-bound scan traffic of the other ~28 blocks per SM)
// ---------------------------------------------------------------------------
__global__ __launch_bounds__(256, 8)
void scan_loss_kernel(const float* __restrict__ onehot,
                      const float* __restrict__ feat,
                      const float* __restrict__ centers,
                      float* __restrict__ loss_out) {
    const int b = blockIdx.x;
    const int t = threadIdx.x;

    __shared__ int s_label;
    __shared__ float s_red[8];
    if (t == 0) s_label = -1;
    __syncthreads();

    const float4* row = reinterpret_cast<const float4*>(onehot + (size_t)b * NCLS);
    const int NV4 = NCLS / 4;  // 2500 float4s

    // 8 KB chunks: 512 float4s per iteration -> 5 iterations max
    #pragma unroll 1
    for (int it = 0; it < (NV4 + 511) / 512; ++it) {
        const int i0 = it * 512 + t;
        const int i1 = i0 + 256;
        float4 v0 = make_float4(0.f, 0.f, 0.f, 0.f);
        float4 v1 = make_float4(0.f, 0.f, 0.f, 0.f);
        if (i0 < NV4) v0 = row[i0];          // both loads in flight (MLP=2)
        if (i1 < NV4) v1 = row[i1];
        int found = -1;
        if (v0.x != 0.f)      found = 4 * i0 + 0;
        else if (v0.y != 0.f) found = 4 * i0 + 1;
        else if (v0.z != 0.f) found = 4 * i0 + 2;
        else if (v0.w != 0.f) found = 4 * i0 + 3;
        else if (v1.x != 0.f) found = 4 * i1 + 0;
        else if (v1.y != 0.f) found = 4 * i1 + 1;
        else if (v1.z != 0.f) found = 4 * i1 + 2;
        else if (v1.w != 0.f) found = 4 * i1 + 3;
        if (found >= 0) {
            s_label = found;
            g_label[b] = found;
            int slot = atomicAdd(&g_cnt[found], 1);
            if (slot < CAP) g_rows[found * CAP + slot] = b;
        }
        __syncthreads();
        if (s_label >= 0) break;
    }

    const int label = s_label;

    // loss vs OLD centers (thread t owns dim t)
    float f = feat[(size_t)b * DIM + t];
    float c = centers[(size_t)label * DIM + t];
    float d = f - c;
    float sq = d * d;
    #pragma unroll
    for (int off = 16; off > 0; off >>= 1)
        sq += __shfl_down_sync(0xFFFFFFFFu, sq, off);
    if ((t & 31) == 0) s_red[t >> 5] = sq;
    __syncthreads();
    if (t < 8) {
        float v = s_red[t];
        #pragma unroll
        for (int off = 4; off > 0; off >>= 1)
            v += __shfl_down_sync(0xFFu, v, off);
        if (t == 0) loss_out[b] = v;
    }
}

// ---------------------------------------------------------------------------
// K2: one warp per class. out_c = k*centers_c + s * sum(feat rows of class c)
//     k = 1 - ALPHA*n/(n+1), s = ALPHA/(n+1). Atomic-free, single write.
//     Also restores g_cnt[c] = 0 for the next graph replay.
// ---------------------------------------------------------------------------
__global__ __launch_bounds__(256)
void scale_gather_kernel(const float* __restrict__ centers,
                         const float* __restrict__ feat,
                         float* __restrict__ out_centers) {
    const int warp = (blockIdx.x * blockDim.x + threadIdx.x) >> 5;
    if (warp >= NCLS) return;
    const int lane = threadIdx.x & 31;

    const int n = g_cnt[warp];
    if (lane == 0) g_cnt[warp] = 0;  // self-clean for next replay

    const float fn = (float)n;
    const float k = 1.0f - ALPHA * fn / (fn + 1.0f);
    const float s = ALPHA / (fn + 1.0f);

    const float4* crow = reinterpret_cast<const float4*>(centers + (size_t)warp * DIM);
    float4 a0 = crow[lane];
    float4 a1 = crow[lane + 32];
    a0.x *= k; a0.y *= k; a0.z *= k; a0.w *= k;
    a1.x *= k; a1.y *= k; a1.z *= k; a1.w *= k;

    if (n > 0) {
        if (n <= CAP) {
            #pragma unroll 1
            for (int j = 0; j < n; ++j) {
                int b = g_rows[warp * CAP + j];
                const float4* fr = reinterpret_cast<const float4*>(feat + (size_t)b * DIM);
                float4 f0 = fr[lane];
                float4 f1 = fr[lane + 32];
                a0.x += s * f0.x; a0.y += s * f0.y; a0.z += s * f0.z; a0.w += s * f0.w;
                a1.x += s * f1.x; a1.y += s * f1.y; a1.z += s * f1.z; a1.w += s * f1.w;
            }
        } else {
            // exhaustive fallback (statistically unreachable; exact correctness)
            #pragma unroll 1
            for (int b = 0; b < BATCH; ++b) {
                if (g_label[b] == warp) {
                    const float4* fr = reinterpret_cast<const float4*>(feat + (size_t)b * DIM);
                    float4 f0 = fr[lane];
                    float4 f1 = fr[lane + 32];
                    a0.x += s * f0.x; a0.y += s * f0.y; a0.z += s * f0.z; a0.w += s * f0.w;
                    a1.x += s * f1.x; a1.y += s * f1.y; a1.z += s * f1.z; a1.w += s * f1.w;
                }
            }
        }
    }

    float4* orow = reinterpret_cast<float4*>(out_centers + (size_t)warp * DIM);
    orow[lane]      = a0;
    orow[lane + 32] = a1;
}

// ---------------------------------------------------------------------------
extern "C" void kernel_launch(void* const* d_in, const int* in_sizes, int n_in,
                              void* d_out, int out_size) {
    const float* feat    = (const float*)d_in[0];  // [4096, 256]
    const float* onehot  = (const float*)d_in[1];  // [4096, 10000]
    const float* centers = (const float*)d_in[2];  // [10000, 256]

    float* loss_out    = (float*)d_out;            // [4096]
    float* centers_out = (float*)d_out + BATCH;    // [10000, 256]

    scan_loss_kernel<<<BATCH, 256>>>(onehot, feat, centers, loss_out);
    // 10000 classes, one warp each -> 1250 blocks of 256 threads
    scale_gather_kernel<<<(NCLS * 32 + 255) / 256, 256>>>(centers, feat, centers_out);
}

// round 7
// speedup vs baseline: 1.5144x; 1.1082x over previous
#include <cuda_runtime.h>

#define BATCH 4096
#define NCLS  10000
#define DIM   256
#define ALPHA 0.5f
#define CAP   64   // per-class row-list capacity (overflow handled exactly)

// Scratch (allocation-free: __device__ globals).
// g_cnt starts zeroed (static init) and is RESTORED to zero by
// scale_gather_kernel at the end of every execution -> no zero kernel needed.
__device__ int g_cnt[NCLS];         // per-class sample count
__device__ int g_label[BATCH];      // decoded label per row (overflow fallback)
__device__ int g_rows[NCLS * CAP];  // per-class row index list (8B aligned rows)

// ---------------------------------------------------------------------------
// K1: one block per batch row.
//  a) early-exit scan of the onehot row, 8 KB chunks (2 float4 per thread per
//     iteration -> MLP=2)
//  b) finder thread: record label, append row to class list, bump count
//  c) all threads: loss ||feat - centers[label]||^2 (gather latency hides
//     under the BW-bound scan traffic of other resident blocks)
// ---------------------------------------------------------------------------
__global__ __launch_bounds__(256, 8)
void scan_loss_kernel(const float* __restrict__ onehot,
                      const float* __restrict__ feat,
                      const float* __restrict__ centers,
                      float* __restrict__ loss_out) {
    const int b = blockIdx.x;
    const int t = threadIdx.x;

    __shared__ int s_label;
    __shared__ float s_red[8];
    if (t == 0) s_label = -1;
    __syncthreads();

    const float4* row = reinterpret_cast<const float4*>(onehot + (size_t)b * NCLS);
    const int NV4 = NCLS / 4;  // 2500 float4s

    #pragma unroll 1
    for (int it = 0; it < (NV4 + 511) / 512; ++it) {
        const int i0 = it * 512 + t;
        const int i1 = i0 + 256;
        float4 v0 = make_float4(0.f, 0.f, 0.f, 0.f);
        float4 v1 = make_float4(0.f, 0.f, 0.f, 0.f);
        if (i0 < NV4) v0 = row[i0];          // both loads in flight (MLP=2)
        if (i1 < NV4) v1 = row[i1];
        int found = -1;
        if (v0.x != 0.f)      found = 4 * i0 + 0;
        else if (v0.y != 0.f) found = 4 * i0 + 1;
        else if (v0.z != 0.f) found = 4 * i0 + 2;
        else if (v0.w != 0.f) found = 4 * i0 + 3;
        else if (v1.x != 0.f) found = 4 * i1 + 0;
        else if (v1.y != 0.f) found = 4 * i1 + 1;
        else if (v1.z != 0.f) found = 4 * i1 + 2;
        else if (v1.w != 0.f) found = 4 * i1 + 3;
        if (found >= 0) {
            s_label = found;
            g_label[b] = found;
            int slot = atomicAdd(&g_cnt[found], 1);
            if (slot < CAP) g_rows[found * CAP + slot] = b;
        }
        __syncthreads();
        if (s_label >= 0) break;
    }

    const int label = s_label;

    // loss vs OLD centers (thread t owns dim t)
    float f = feat[(size_t)b * DIM + t];
    float c = centers[(size_t)label * DIM + t];
    float d = f - c;
    float sq = d * d;
    #pragma unroll
    for (int off = 16; off > 0; off >>= 1)
        sq += __shfl_down_sync(0xFFFFFFFFu, sq, off);
    if ((t & 31) == 0) s_red[t >> 5] = sq;
    __syncthreads();
    if (t < 8) {
        float v = s_red[t];
        #pragma unroll
        for (int off = 4; off > 0; off >>= 1)
            v += __shfl_down_sync(0xFFu, v, off);
        if (t == 0) loss_out[b] = v;
    }
}

// ---------------------------------------------------------------------------
// K2: one thread per float4 of the [C, D] centers matrix (640000 threads).
//   out = k*centers + s * sum(feat rows of class)   k=1-a*n/(n+1), s=a/(n+1)
// Class rows (64 threads) align with blocks (256 threads), so the g_cnt
// self-clean is ordered with a single __syncthreads() after ALL threads of
// the block have read their class count (fixes the round-6 race: a class
// spans 2 warps, and warp B could read after warp A's col==0 zeroed it).
// Level-0 loads (g_cnt, first two g_rows slots, centers float4) are
// independent; feat gathers are the single dependent level, MLP=2 for the
// dominant n<=2 case.
// ---------------------------------------------------------------------------
__global__ __launch_bounds__(256)
void scale_gather_kernel(const float* __restrict__ centers,
                         const float* __restrict__ feat,
                         float* __restrict__ out_centers) {
    const int i = blockIdx.x * blockDim.x + threadIdx.x;  // float4 index
    const int N4 = NCLS * DIM / 4;                        // 640000
    if (i >= N4) return;
    const int c   = i >> 6;   // class (64 float4 per class row)
    const int col = i & 63;   // float4 column within class row

    // --- level 0: all independent loads ---
    const int n = g_cnt[c];
    const int2 r01 = *reinterpret_cast<const int2*>(&g_rows[c * CAP]);  // speculative
    float4 a = reinterpret_cast<const float4*>(centers)[i];

    // self-clean for next graph replay — AFTER every thread in the block
    // (class spans 2 warps of this block) has read its count.
    __syncthreads();
    if (col == 0) g_cnt[c] = 0;

    const float fn = (float)n;
    const float k = 1.0f - ALPHA * fn / (fn + 1.0f);
    const float s = ALPHA / (fn + 1.0f);
    a.x *= k; a.y *= k; a.z *= k; a.w *= k;

    const float4* feat4 = reinterpret_cast<const float4*>(feat);

    // --- level 1: feat gathers (n<=2 covers 99.4%; both loads co-issued) ---
    if (n >= 1) {
        float4 f0 = feat4[(size_t)r01.x * 64 + col];
        float4 f1 = (n >= 2) ? feat4[(size_t)r01.y * 64 + col]
                             : make_float4(0.f, 0.f, 0.f, 0.f);
        a.x += s * (f0.x + f1.x);
        a.y += s * (f0.y + f1.y);
        a.z += s * (f0.z + f1.z);
        a.w += s * (f0.w + f1.w);
        if (n > 2) {
            const int m = (n <= CAP) ? n : CAP;
            #pragma unroll 1
            for (int j = 2; j < m; ++j) {
                int b = g_rows[c * CAP + j];
                float4 f = feat4[(size_t)b * 64 + col];
                a.x += s * f.x; a.y += s * f.y; a.z += s * f.z; a.w += s * f.w;
            }
            if (n > CAP) {
                // exhaustive fallback (statistically unreachable; exact)
                #pragma unroll 1
                for (int b = 0; b < BATCH; ++b) {
                    if (g_label[b] == c) {
                        bool seen = false;
                        for (int j = 0; j < CAP; ++j)
                            if (g_rows[c * CAP + j] == b) { seen = true; break; }
                        if (!seen) {
                            float4 f = feat4[(size_t)b * 64 + col];
                            a.x += s * f.x; a.y += s * f.y;
                            a.z += s * f.z; a.w += s * f.w;
                        }
                    }
                }
            }
        }
    }

    reinterpret_cast<float4*>(out_centers)[i] = a;
}

// ---------------------------------------------------------------------------
extern "C" void kernel_launch(void* const* d_in, const int* in_sizes, int n_in,
                              void* d_out, int out_size) {
    const float* feat    = (const float*)d_in[0];  // [4096, 256]
    const float* onehot  = (const float*)d_in[1];  // [4096, 10000]
    const float* centers = (const float*)d_in[2];  // [10000, 256]

    float* loss_out    = (float*)d_out;            // [4096]
    float* centers_out = (float*)d_out + BATCH;    // [10000, 256]

    scan_loss_kernel<<<BATCH, 256>>>(onehot, feat, centers, loss_out);
    scale_gather_kernel<<<(NCLS * DIM / 4 + 255) / 256, 256>>>(
        centers, feat, centers_out);
}